// round 16
// baseline (speedup 1.0000x reference)
#include <cuda_runtime.h>
#include <cuda_pipeline_primitives.h>

#define DIM 64
#define KNB 16
#define NREL 33
#define W0PAD 17   // float4 per row (68 floats) -> conflict-free LDS
#define XSTR 68    // x_s row stride in floats (bank-staggered like W0)

__device__ __forceinline__ unsigned f2tf(float x) {
    unsigned r; asm("cvt.rna.tf32.f32 %0, %1;" : "=r"(r) : "f"(x)); return r;
}
__device__ __forceinline__ void mma_tf32(float& d0, float& d1, float& d2, float& d3,
                                         unsigned a0, unsigned a1, unsigned a2, unsigned a3,
                                         unsigned b0, unsigned b1) {
    asm volatile("mma.sync.aligned.m16n8k8.row.col.f32.tf32.tf32.f32 "
                 "{%0,%1,%2,%3},{%4,%5,%6,%7},{%8,%9},{%0,%1,%2,%3};"
                 : "+f"(d0), "+f"(d1), "+f"(d2), "+f"(d3)
                 : "r"(a0), "r"(a1), "r"(a2), "r"(a3), "r"(b0), "r"(b1));
}

__global__ __launch_bounds__(256, 5) void kgnn_kernel(
    const int* __restrict__ u_ids,
    const int* __restrict__ i_ids,
    const int* __restrict__ adj_entity,
    const int* __restrict__ adj_relation,
    const float* __restrict__ user_emb,
    const float* __restrict__ entity_emb,
    const float* __restrict__ relation_emb,
    const float* __restrict__ W0,
    const float* __restrict__ b0,
    const float* __restrict__ W1,
    const float* __restrict__ b1,
    float* __restrict__ out,
    int B)
{
    // flat groups: g = elem*16 + j for hop-1 (g<32); g = 32+elem for hop-0
    __shared__ float4 W0_s[64 * W0PAD];
    __shared__ float  ue_s[2][64];
    __shared__ float  ex_s[2][NREL];
    __shared__ float  attn_g[34][16];
    __shared__ int    eg_s[34][16];
    __shared__ int    self_s[34];
    __shared__ int    e1_s[2][16], r0_s[2][16];
    __shared__ __align__(16) float x_s[48 * XSTR];   // X rows 0..33 (+pad), then h in-place
    __shared__ __align__(16) float xf_s[2][64];
    __shared__ float  red_s[8];

    const int b    = blockIdx.x;
    const int t    = threadIdx.x;
    const int lane = t & 31;
    const int w    = t >> 5;
    const int bi0  = 2 * b;
    const int bi1  = (2 * b + 1 < B) ? (2 * b + 1) : (B - 1);

    // ---- P1: async-stage W0, ue x2, indices, zero X pad rows ----
    {
        const float4* W0_4 = (const float4*)W0;
        #pragma unroll
        for (int i = 0; i < 4; i++) {
            int idx = t + i * 256;
            int e = idx >> 4, c4 = idx & 15;
            __pipeline_memcpy_async(&W0_s[e * W0PAD + c4], &W0_4[idx], 16);
        }
        __pipeline_commit();
    }
    for (int i = t; i < 14 * XSTR; i += 256) x_s[34 * XSTR + i] = 0.f;  // pad rows
    if (t < 128) {
        const int elem = t >> 6, d = t & 63;
        const int bi = elem ? bi1 : bi0;
        ue_s[elem][d] = user_emb[u_ids[bi] * 64 + d];
    }
    if (t < 32) {
        const int elem = t >> 4, kk = t & 15;
        const int bi = elem ? bi1 : bi0;
        const int e0 = i_ids[bi];
        e1_s[elem][kk] = adj_entity[e0 * KNB + kk];
        r0_s[elem][kk] = adj_relation[e0 * KNB + kk];
    }
    if (t < 2) self_s[32 + t] = i_ids[t ? bi1 : bi0];
    __syncthreads();

    // ---- P2: 66 relation exp-dots + group tables ----
    for (int idx = w; idx < 2 * NREL; idx += 8) {
        const int r = idx >> 1, elem = idx & 1;
        float p = ue_s[elem][lane] * relation_emb[r * 64 + lane]
                + ue_s[elem][lane + 32] * relation_emb[r * 64 + 32 + lane];
        #pragma unroll
        for (int o = 16; o; o >>= 1) p += __shfl_xor_sync(0xffffffffu, p, o);
        if (lane == 0) ex_s[elem][r] = __expf(p * (1.f / 64.f));
    }
    int rr0, rr1;
    {
        const int j = t >> 4, k = t & 15;
        const int ej0 = e1_s[0][j];
        eg_s[j][k] = adj_entity[ej0 * KNB + k];
        rr0 = adj_relation[ej0 * KNB + k];
        const int ej1 = e1_s[1][j];
        eg_s[16 + j][k] = adj_entity[ej1 * KNB + k];
        rr1 = adj_relation[ej1 * KNB + k];
    }
    if (t < 32) {
        const int elem = t >> 4, j = t & 15;
        self_s[t] = e1_s[0][j];                 // overwritten below for t>=16
        eg_s[32 + elem][j] = e1_s[elem][j];     // hop-0 neighbors
    }
    if (t >= 32 && t < 48) self_s[t - 16] = e1_s[1][t - 32];
    __syncthreads();

    // ---- P3: attention: exp lookup + 16-lane sum + divide ----
    {
        const int j = t >> 4, k = t & 15;
        #pragma unroll
        for (int elem = 0; elem < 2; elem++) {
            float ex = ex_s[elem][elem ? rr1 : rr0];
            float sum = ex;
            #pragma unroll
            for (int o = 8; o; o >>= 1) sum += __shfl_xor_sync(0xffffffffu, sum, o);
            attn_g[elem * 16 + j][k] = __fdividef(ex, sum * 16.f);
        }
    }
    if (t < 32) {
        const int elem = t >> 4, k = t & 15;
        float ex = ex_s[elem][r0_s[elem][k]];
        float sum = ex;
        #pragma unroll
        for (int o = 8; o; o >>= 1) sum += __shfl_xor_sync(0xffffffffu, sum, o);
        attn_g[32 + elem][k] = __fdividef(ex, sum * 16.f);
    }
    __pipeline_wait_prior(0);   // W0 staged; published at the barrier below
    __syncthreads();

    // ---- P4: unified float4 gathers over 34 groups (warp-owned slots) ----
    const int half = lane >> 4;
    const int c    = lane & 15;
    #pragma unroll
    for (int jj = 0; jj < 4; jj++) {
        const int g = 4 * w + jj;
        float4 acc = make_float4(0.f, 0.f, 0.f, 0.f);
        #pragma unroll
        for (int kk = 0; kk < 8; kk++) {
            const int k = kk * 2 + half;
            const float4 v = ((const float4*)(entity_emb + eg_s[g][k] * 64))[c];
            const float a = attn_g[g][k];
            acc.x += a * v.x; acc.y += a * v.y; acc.z += a * v.z; acc.w += a * v.w;
        }
        acc.x += __shfl_xor_sync(0xffffffffu, acc.x, 16);
        acc.y += __shfl_xor_sync(0xffffffffu, acc.y, 16);
        acc.z += __shfl_xor_sync(0xffffffffu, acc.z, 16);
        acc.w += __shfl_xor_sync(0xffffffffu, acc.w, 16);
        if (half == 0) {
            const float4 sv = ((const float4*)(entity_emb + self_s[g] * 64))[c];
            ((float4*)(x_s + g * XSTR))[c] = make_float4(sv.x + acc.x, sv.y + acc.y,
                                                         sv.z + acc.z, sv.w + acc.w);
        }
    }
    if (w >= 6) {   // g = 32 (w=6), 33 (w=7)
        const int g = 26 + w;
        float4 acc = make_float4(0.f, 0.f, 0.f, 0.f);
        #pragma unroll
        for (int kk = 0; kk < 8; kk++) {
            const int k = kk * 2 + half;
            const float4 v = ((const float4*)(entity_emb + eg_s[g][k] * 64))[c];
            const float a = attn_g[g][k];
            acc.x += a * v.x; acc.y += a * v.y; acc.z += a * v.z; acc.w += a * v.w;
        }
        acc.x += __shfl_xor_sync(0xffffffffu, acc.x, 16);
        acc.y += __shfl_xor_sync(0xffffffffu, acc.y, 16);
        acc.z += __shfl_xor_sync(0xffffffffu, acc.z, 16);
        acc.w += __shfl_xor_sync(0xffffffffu, acc.w, 16);
        if (half == 0) {
            const float4 sv = ((const float4*)(entity_emb + self_s[g] * 64))[c];
            ((float4*)(x_s + g * XSTR))[c] = make_float4(sv.x + acc.x, sv.y + acc.y,
                                                         sv.z + acc.z, sv.w + acc.w);
        }
    }
    __syncthreads();   // all X rows visible block-wide (GEMM reads all rows)

    // ---- P5a: H = X @ W0^T via tensor cores; warp w owns n8 column tile 8w.
    //           3xTF32 compensation; D accumulates in registers. ----
    const int g  = lane >> 2;       // 0..7
    const int l4 = lane & 3;        // 0..3
    const int n0 = w * 8;
    float D[3][4];
    #pragma unroll
    for (int m = 0; m < 3; m++)
        #pragma unroll
        for (int q = 0; q < 4; q++) D[m][q] = 0.f;
    {
        const float* W0f = (const float*)W0_s;
        #pragma unroll
        for (int k8 = 0; k8 < 8; k8++) {
            const int kb = k8 * 8;
            // B frag: B[d][e] = W0[e][d]; col-major col e = W0_s row e
            const float bf0 = W0f[(n0 + g) * 68 + kb + l4];
            const float bf1 = W0f[(n0 + g) * 68 + kb + 4 + l4];
            const unsigned bh0 = f2tf(bf0), bh1 = f2tf(bf1);
            const unsigned bl0 = f2tf(bf0 - __uint_as_float(bh0));
            const unsigned bl1 = f2tf(bf1 - __uint_as_float(bh1));
            #pragma unroll
            for (int m = 0; m < 3; m++) {
                const int r0 = (m * 16 + g) * XSTR, r8 = (m * 16 + 8 + g) * XSTR;
                const float a0 = x_s[r0 + kb + l4];
                const float a1 = x_s[r8 + kb + l4];
                const float a2 = x_s[r0 + kb + 4 + l4];
                const float a3 = x_s[r8 + kb + 4 + l4];
                const unsigned h0 = f2tf(a0), h1 = f2tf(a1), h2 = f2tf(a2), h3 = f2tf(a3);
                const unsigned o0 = f2tf(a0 - __uint_as_float(h0));
                const unsigned o1 = f2tf(a1 - __uint_as_float(h1));
                const unsigned o2 = f2tf(a2 - __uint_as_float(h2));
                const unsigned o3 = f2tf(a3 - __uint_as_float(h3));
                mma_tf32(D[m][0], D[m][1], D[m][2], D[m][3], h0, h1, h2, h3, bh0, bh1);
                mma_tf32(D[m][0], D[m][1], D[m][2], D[m][3], h0, h1, h2, h3, bl0, bl1);
                mma_tf32(D[m][0], D[m][1], D[m][2], D[m][3], o0, o1, o2, o3, bh0, bh1);
            }
        }
    }
    __syncthreads();   // all X reads done before in-place H writes

    // ---- P5b: bias + relu + in-place store (rows < 34 only) ----
    {
        const int col0 = n0 + 2 * l4, col1 = col0 + 1;
        const float bb0 = b0[col0], bb1 = b0[col1];
        #pragma unroll
        for (int m = 0; m < 3; m++) {
            const int r0 = m * 16 + g, r1 = r0 + 8;
            if (r0 < 34) {
                x_s[r0 * XSTR + col0] = fmaxf(D[m][0] + bb0, 0.f);
                x_s[r0 * XSTR + col1] = fmaxf(D[m][1] + bb1, 0.f);
            }
            if (r1 < 34) {
                x_s[r1 * XSTR + col0] = fmaxf(D[m][2] + bb0, 0.f);
                x_s[r1 * XSTR + col1] = fmaxf(D[m][3] + bb1, 0.f);
            }
        }
    }
    __syncthreads();

    // ---- P6a: layer-1 hop-0 combine ----
    if (t < 128) {
        const int elem = t >> 6, d = t & 63;
        float agg = 0.f;
        #pragma unroll
        for (int k = 0; k < 16; k++)
            agg += attn_g[32 + elem][k] * x_s[(elem * 16 + k) * XSTR + d];
        xf_s[elem][d] = x_s[(32 + elem) * XSTR + d] + agg;
    }
    __syncthreads();

    // ---- P6b: tanh matvec + score, ALL 8 warps (dd split by lane half) ----
    {
        const int i    = w * 16 + (lane & 15);   // 0..127
        const int elem = i >> 6, d = i & 63;
        const int dh   = lane >> 4;
        float acc = (dh == 0) ? b1[d] : 0.f;
        const float4* w1r = (const float4*)(W1 + d * 64);
        const float4* x0v = (const float4*)xf_s[elem];
        #pragma unroll
        for (int q = 0; q < 8; q++) {
            const int dd = dh * 8 + q;
            const float4 xv = x0v[dd];
            const float4 wv = w1r[dd];
            acc += xv.x * wv.x + xv.y * wv.y + xv.z * wv.z + xv.w * wv.w;
        }
        acc += __shfl_xor_sync(0xffffffffu, acc, 16);
        const float item = tanhf(acc);
        float p = ue_s[elem][d] * item;
        #pragma unroll
        for (int o = 8; o; o >>= 1) p += __shfl_xor_sync(0xffffffffu, p, o);
        if (lane == 0) red_s[w] = p;
    }
    __syncthreads();
    if (t < 2) {
        const int bi = 2 * b + t;
        if (bi < B) {
            const float s = red_s[t * 4] + red_s[t * 4 + 1]
                          + red_s[t * 4 + 2] + red_s[t * 4 + 3];
            out[bi] = 1.f / (1.f + __expf(-s));
        }
    }
}

extern "C" void kernel_launch(void* const* d_in, const int* in_sizes, int n_in,
                              void* d_out, int out_size) {
    const int*   u_ids        = (const int*)d_in[0];
    const int*   i_ids        = (const int*)d_in[1];
    const int*   adj_entity   = (const int*)d_in[2];
    const int*   adj_relation = (const int*)d_in[3];
    const float* user_emb     = (const float*)d_in[4];
    const float* entity_emb   = (const float*)d_in[5];
    const float* relation_emb = (const float*)d_in[6];
    const float* W0           = (const float*)d_in[7];
    const float* b0           = (const float*)d_in[8];
    const float* W1           = (const float*)d_in[9];
    const float* b1           = (const float*)d_in[10];
    float* out = (float*)d_out;

    const int B = in_sizes[1];
    const int grid = (B + 1) / 2;
    kgnn_kernel<<<grid, 256>>>(u_ids, i_ids, adj_entity, adj_relation,
                               user_emb, entity_emb, relation_emb,
                               W0, b0, W1, b1, out, B);
}

// round 17
// speedup vs baseline: 1.1276x; 1.1276x over previous
#include <cuda_runtime.h>

#define DIM 64
#define KNB 16
#define NREL 33
#define USTR 36    // packed bf16x2 row stride in uints (32 data + 4 pad) -> 4g+l4 banks
#define HSTR 68    // h row stride in floats

__device__ __forceinline__ unsigned pkbf(float lo_e, float hi_e) {
    unsigned r; asm("cvt.rn.bf16x2.f32 %0, %1, %2;" : "=r"(r) : "f"(hi_e), "f"(lo_e)); return r;
}
__device__ __forceinline__ float bflo(unsigned p) { return __uint_as_float(p << 16); }
__device__ __forceinline__ float bfhi(unsigned p) { return __uint_as_float(p & 0xFFFF0000u); }

__device__ __forceinline__ void mma_bf16(float& d0, float& d1, float& d2, float& d3,
                                         unsigned a0, unsigned a1, unsigned a2, unsigned a3,
                                         unsigned b0, unsigned b1) {
    asm volatile("mma.sync.aligned.m16n8k16.row.col.f32.bf16.bf16.f32 "
                 "{%0,%1,%2,%3},{%4,%5,%6,%7},{%8,%9},{%0,%1,%2,%3};"
                 : "+f"(d0), "+f"(d1), "+f"(d2), "+f"(d3)
                 : "r"(a0), "r"(a1), "r"(a2), "r"(a3), "r"(b0), "r"(b1));
}

__global__ __launch_bounds__(256, 5) void kgnn_kernel(
    const int* __restrict__ u_ids,
    const int* __restrict__ i_ids,
    const int* __restrict__ adj_entity,
    const int* __restrict__ adj_relation,
    const float* __restrict__ user_emb,
    const float* __restrict__ entity_emb,
    const float* __restrict__ relation_emb,
    const float* __restrict__ W0,
    const float* __restrict__ b0,
    const float* __restrict__ W1,
    const float* __restrict__ b1,
    float* __restrict__ out,
    int B)
{
    // flat groups: g = elem*16 + j for hop-1 (g<32); g = 32+elem for hop-0
    __shared__ unsigned W0h_s[64 * USTR];
    __shared__ unsigned W0l_s[64 * USTR];
    __shared__ __align__(16) unsigned char xbuf[48 * USTR * 4 * 2];  // Xh+Xl, later h
    __shared__ float  ue_s[2][64];
    __shared__ float  ex_s[2][NREL];
    __shared__ float  attn_g[34][16];
    __shared__ int    eg_s[34][16];
    __shared__ int    self_s[34];
    __shared__ int    e1_s[2][16], r0_s[2][16];
    __shared__ __align__(16) float xf_s[2][64];
    __shared__ float  red_s[8];

    unsigned* Xh = (unsigned*)xbuf;
    unsigned* Xl = (unsigned*)(xbuf + 48 * USTR * 4);
    float*    h_s = (float*)xbuf;                   // overlay; live after GEMM

    const int b    = blockIdx.x;
    const int t    = threadIdx.x;
    const int lane = t & 31;
    const int w    = t >> 5;
    const int bi0  = 2 * b;
    const int bi1  = (2 * b + 1 < B) ? (2 * b + 1) : (B - 1);

    // ---- P1: W0 -> bf16 hi/lo smem; ue x2; indices; zero X pad rows ----
    {
        const float4* W0_4 = (const float4*)W0;
        #pragma unroll
        for (int i = 0; i < 4; i++) {
            int idx = t + i * 256;                 // 1024 float4
            int e = idx >> 4, c4 = idx & 15;       // pair base 2*c4
            const float4 v = W0_4[idx];
            const unsigned hA = pkbf(v.x, v.y), hB = pkbf(v.z, v.w);
            const unsigned lA = pkbf(v.x - bflo(hA), v.y - bfhi(hA));
            const unsigned lB = pkbf(v.z - bflo(hB), v.w - bfhi(hB));
            ((uint2*)(W0h_s + e * USTR + 2 * c4))[0] = make_uint2(hA, hB);
            ((uint2*)(W0l_s + e * USTR + 2 * c4))[0] = make_uint2(lA, lB);
        }
    }
    for (int i = t; i < 14 * USTR; i += 256) {      // zero pad rows 34..47
        Xh[34 * USTR + i] = 0u;
        Xl[34 * USTR + i] = 0u;
    }
    if (t < 128) {
        const int elem = t >> 6, d = t & 63;
        const int bi = elem ? bi1 : bi0;
        ue_s[elem][d] = user_emb[u_ids[bi] * 64 + d];
    }
    if (t < 32) {
        const int elem = t >> 4, kk = t & 15;
        const int bi = elem ? bi1 : bi0;
        const int e0 = i_ids[bi];
        e1_s[elem][kk] = adj_entity[e0 * KNB + kk];
        r0_s[elem][kk] = adj_relation[e0 * KNB + kk];
    }
    if (t < 2) self_s[32 + t] = i_ids[t ? bi1 : bi0];
    __syncthreads();

    // ---- P2: 66 relation exp-dots + group tables ----
    for (int idx = w; idx < 2 * NREL; idx += 8) {
        const int r = idx >> 1, elem = idx & 1;
        float p = ue_s[elem][lane] * relation_emb[r * 64 + lane]
                + ue_s[elem][lane + 32] * relation_emb[r * 64 + 32 + lane];
        #pragma unroll
        for (int o = 16; o; o >>= 1) p += __shfl_xor_sync(0xffffffffu, p, o);
        if (lane == 0) ex_s[elem][r] = __expf(p * (1.f / 64.f));
    }
    int rr0, rr1;
    {
        const int j = t >> 4, k = t & 15;
        const int ej0 = e1_s[0][j];
        eg_s[j][k] = adj_entity[ej0 * KNB + k];
        rr0 = adj_relation[ej0 * KNB + k];
        const int ej1 = e1_s[1][j];
        eg_s[16 + j][k] = adj_entity[ej1 * KNB + k];
        rr1 = adj_relation[ej1 * KNB + k];
    }
    if (t < 32) {
        const int elem = t >> 4, j = t & 15;
        self_s[t] = e1_s[0][j];                 // overwritten below for t>=16
        eg_s[32 + elem][j] = e1_s[elem][j];     // hop-0 neighbors
    }
    if (t >= 32 && t < 48) self_s[t - 16] = e1_s[1][t - 32];
    __syncthreads();

    // ---- P3: attention: exp lookup + 16-lane sum + divide ----
    {
        const int j = t >> 4, k = t & 15;
        #pragma unroll
        for (int elem = 0; elem < 2; elem++) {
            float ex = ex_s[elem][elem ? rr1 : rr0];
            float sum = ex;
            #pragma unroll
            for (int o = 8; o; o >>= 1) sum += __shfl_xor_sync(0xffffffffu, sum, o);
            attn_g[elem * 16 + j][k] = __fdividef(ex, sum * 16.f);
        }
    }
    if (t < 32) {
        const int elem = t >> 4, k = t & 15;
        float ex = ex_s[elem][r0_s[elem][k]];
        float sum = ex;
        #pragma unroll
        for (int o = 8; o; o >>= 1) sum += __shfl_xor_sync(0xffffffffu, sum, o);
        attn_g[32 + elem][k] = __fdividef(ex, sum * 16.f);
    }
    __syncthreads();

    // ---- P4: gathers over 34 groups; write X as packed bf16 hi/lo ----
    const int half = lane >> 4;
    const int c    = lane & 15;
    #pragma unroll
    for (int jj = 0; jj < 5; jj++) {
        int g;
        if (jj < 4)       g = 4 * w + jj;
        else if (w >= 6)  g = 26 + w;              // 5th group: g = 32, 33
        else              break;
        float4 acc = make_float4(0.f, 0.f, 0.f, 0.f);
        #pragma unroll
        for (int kk = 0; kk < 8; kk++) {
            const int k = kk * 2 + half;
            const float4 v = ((const float4*)(entity_emb + eg_s[g][k] * 64))[c];
            const float a = attn_g[g][k];
            acc.x += a * v.x; acc.y += a * v.y; acc.z += a * v.z; acc.w += a * v.w;
        }
        acc.x += __shfl_xor_sync(0xffffffffu, acc.x, 16);
        acc.y += __shfl_xor_sync(0xffffffffu, acc.y, 16);
        acc.z += __shfl_xor_sync(0xffffffffu, acc.z, 16);
        acc.w += __shfl_xor_sync(0xffffffffu, acc.w, 16);
        if (half == 0) {
            const float4 sv = ((const float4*)(entity_emb + self_s[g] * 64))[c];
            const float vx = sv.x + acc.x, vy = sv.y + acc.y;
            const float vz = sv.z + acc.z, vw = sv.w + acc.w;
            const unsigned hA = pkbf(vx, vy), hB = pkbf(vz, vw);
            const unsigned lA = pkbf(vx - bflo(hA), vy - bfhi(hA));
            const unsigned lB = pkbf(vz - bflo(hB), vw - bfhi(hB));
            ((uint2*)(Xh + g * USTR + 2 * c))[0] = make_uint2(hA, hB);
            ((uint2*)(Xl + g * USTR + 2 * c))[0] = make_uint2(lA, lB);
        }
    }
    __syncthreads();   // all X rows visible block-wide (GEMM reads all rows)

    // ---- P5a: H = X @ W0^T via bf16 tensor cores (hh + lh + hl) ----
    const int g  = lane >> 2;       // 0..7
    const int l4 = lane & 3;        // 0..3
    const int n0 = w * 8;
    float D[3][4];
    #pragma unroll
    for (int m = 0; m < 3; m++)
        #pragma unroll
        for (int q = 0; q < 4; q++) D[m][q] = 0.f;
    #pragma unroll
    for (int k16 = 0; k16 < 4; k16++) {
        const int pb = k16 * 8;     // pair base within row
        const int brow = (n0 + g) * USTR + pb + l4;
        const unsigned b0h = W0h_s[brow],     b1h = W0h_s[brow + 4];
        const unsigned b0l = W0l_s[brow],     b1l = W0l_s[brow + 4];
        #pragma unroll
        for (int m = 0; m < 3; m++) {
            const int r0 = (m * 16 + g) * USTR + pb + l4;
            const int r8 = (m * 16 + 8 + g) * USTR + pb + l4;
            const unsigned a0h = Xh[r0], a1h = Xh[r8], a2h = Xh[r0 + 4], a3h = Xh[r8 + 4];
            const unsigned a0l = Xl[r0], a1l = Xl[r8], a2l = Xl[r0 + 4], a3l = Xl[r8 + 4];
            mma_bf16(D[m][0], D[m][1], D[m][2], D[m][3], a0h, a1h, a2h, a3h, b0h, b1h);
            mma_bf16(D[m][0], D[m][1], D[m][2], D[m][3], a0l, a1l, a2l, a3l, b0h, b1h);
            mma_bf16(D[m][0], D[m][1], D[m][2], D[m][3], a0h, a1h, a2h, a3h, b0l, b1l);
        }
    }
    __syncthreads();   // all X reads done before h overlay writes

    // ---- P5b: bias + relu + store h (rows < 34) into overlay ----
    {
        const int col0 = n0 + 2 * l4, col1 = col0 + 1;
        const float bb0 = b0[col0], bb1 = b0[col1];
        #pragma unroll
        for (int m = 0; m < 3; m++) {
            const int r0 = m * 16 + g, r1 = r0 + 8;
            if (r0 < 34) {
                h_s[r0 * HSTR + col0] = fmaxf(D[m][0] + bb0, 0.f);
                h_s[r0 * HSTR + col1] = fmaxf(D[m][1] + bb1, 0.f);
            }
            if (r1 < 34) {
                h_s[r1 * HSTR + col0] = fmaxf(D[m][2] + bb0, 0.f);
                h_s[r1 * HSTR + col1] = fmaxf(D[m][3] + bb1, 0.f);
            }
        }
    }
    __syncthreads();

    // ---- P6a: layer-1 hop-0 combine ----
    if (t < 128) {
        const int elem = t >> 6, d = t & 63;
        float agg = 0.f;
        #pragma unroll
        for (int k = 0; k < 16; k++)
            agg += attn_g[32 + elem][k] * h_s[(elem * 16 + k) * HSTR + d];
        xf_s[elem][d] = h_s[(32 + elem) * HSTR + d] + agg;
    }
    __syncthreads();

    // ---- P6b: tanh matvec + score, ALL 8 warps (dd split by lane half) ----
    {
        const int i    = w * 16 + (lane & 15);   // 0..127
        const int elem = i >> 6, d = i & 63;
        const int dh   = lane >> 4;
        float acc = (dh == 0) ? b1[d] : 0.f;
        const float4* w1r = (const float4*)(W1 + d * 64);
        const float4* x0v = (const float4*)xf_s[elem];
        #pragma unroll
        for (int q = 0; q < 8; q++) {
            const int dd = dh * 8 + q;
            const float4 xv = x0v[dd];
            const float4 wv = w1r[dd];
            acc += xv.x * wv.x + xv.y * wv.y + xv.z * wv.z + xv.w * wv.w;
        }
        acc += __shfl_xor_sync(0xffffffffu, acc, 16);
        const float item = tanhf(acc);
        float p = ue_s[elem][d] * item;
        #pragma unroll
        for (int o = 8; o; o >>= 1) p += __shfl_xor_sync(0xffffffffu, p, o);
        if (lane == 0) red_s[w] = p;
    }
    __syncthreads();
    if (t < 2) {
        const int bi = 2 * b + t;
        if (bi < B) {
            const float s = red_s[t * 4] + red_s[t * 4 + 1]
                          + red_s[t * 4 + 2] + red_s[t * 4 + 3];
            out[bi] = 1.f / (1.f + __expf(-s));
        }
    }
}

extern "C" void kernel_launch(void* const* d_in, const int* in_sizes, int n_in,
                              void* d_out, int out_size) {
    const int*   u_ids        = (const int*)d_in[0];
    const int*   i_ids        = (const int*)d_in[1];
    const int*   adj_entity   = (const int*)d_in[2];
    const int*   adj_relation = (const int*)d_in[3];
    const float* user_emb     = (const float*)d_in[4];
    const float* entity_emb   = (const float*)d_in[5];
    const float* relation_emb = (const float*)d_in[6];
    const float* W0           = (const float*)d_in[7];
    const float* b0           = (const float*)d_in[8];
    const float* W1           = (const float*)d_in[9];
    const float* b1           = (const float*)d_in[10];
    float* out = (float*)d_out;

    const int B = in_sizes[1];
    const int grid = (B + 1) / 2;
    kgnn_kernel<<<grid, 256>>>(u_ids, i_ids, adj_entity, adj_relation,
                               user_emb, entity_emb, relation_emb,
                               W0, b0, W1, b1, out, B);
}